// round 9
// baseline (speedup 1.0000x reference)
#include <cuda_runtime.h>
#include <cuda_fp16.h>
#include <cstdint>

// Problem: B=16384, IN_DIM=1024, D=256, C=100
#define Bsz    16384
#define KDIM   1024
#define DDIM   256
#define CNUM   100
#define CPAD   112

#define BM 128
#define BK 64
#define NITER (KDIM / BK)     // 16
#define NT 256                // 8 warps

// fp16-element strides; (stride/2) % 32 == 4 -> conflict-free b32 frag LDS
#define AST 72
#define BST 72
#define ZST 264
#define PST 72

#define A_SLOT_BYTES (BM * AST * 2)       // 18432, 2 slots
#define B_SLOT_BYTES (256 * BST * 2)      // 36864, 3 slots
#define B_OFF (2 * A_SLOT_BYTES)          // 36864
#define DYN_BYTES (B_OFF + 3 * B_SLOT_BYTES)   // 147456

#define ZS_BYTES (BM * ZST * 2)           // 67584 (reuses mainloop smem)
#define PCH_BYTES (CPAD * PST * 2)        // 16128

// Pre-converted fp16 operands (device globals: allocation-free)
__device__ __half g_wt[(size_t)DDIM * KDIM];  // W^T, [n][k]
__device__ __half g_ph[CPAD * DDIM];          // P padded, [c][k]
__device__ float  g_pn[CPAD];                 // |P_c|^2

// ---------------------------------------------------------------------------
__device__ __forceinline__ uint32_t smem_u32(const void* p) {
    uint32_t a;
    asm("{ .reg .u64 t; cvta.to.shared.u64 t, %1; cvt.u32.u64 %0, t; }"
        : "=r"(a) : "l"(p));
    return a;
}

#define CP_ASYNC16(dst, src) \
    asm volatile("cp.async.cg.shared.global [%0], [%1], 16;" \
                 :: "r"(dst), "l"(src) : "memory")
#define CP_COMMIT() asm volatile("cp.async.commit_group;" ::: "memory")
#define CP_WAIT1()  asm volatile("cp.async.wait_group 1;" ::: "memory")
#define CP_WAIT0()  asm volatile("cp.async.wait_group 0;" ::: "memory")

#define MMA_F16(d, a, b) \
    asm volatile("mma.sync.aligned.m16n8k16.row.col.f32.f16.f16.f32 " \
        "{%0,%1,%2,%3}, {%4,%5,%6,%7}, {%8,%9}, {%0,%1,%2,%3};" \
        : "+f"((d)[0]), "+f"((d)[1]), "+f"((d)[2]), "+f"((d)[3]) \
        : "r"((a)[0]), "r"((a)[1]), "r"((a)[2]), "r"((a)[3]), \
          "r"((b)[0]), "r"((b)[1]))

// ---------------------------------------------------------------------------
// Pre-pass (small): W transpose->fp16, P pad->fp16 + |P|^2.
// ---------------------------------------------------------------------------
#define WBLKS 256
#define PBLKS 14
#define PREP_GRID (WBLKS + PBLKS)

__global__ void __launch_bounds__(256)
prep_kernel(const float* __restrict__ W,
            const float* __restrict__ P)
{
    const int b   = blockIdx.x;
    const int tid = threadIdx.x;

    if (b < WBLKS) {
        __shared__ float t[32][33];
        const int bx = (b & 7) * 32;    // n
        const int by = (b >> 3) * 32;   // k
        const int tx = tid & 31, ty = tid >> 5;
#pragma unroll
        for (int j = 0; j < 32; j += 8)
            t[ty + j][tx] = W[(size_t)(by + ty + j) * DDIM + bx + tx];
        __syncthreads();
#pragma unroll
        for (int j = 0; j < 32; j += 8)
            g_wt[(size_t)(bx + ty + j) * KDIM + by + tx] =
                __float2half_rn(t[tx][ty + j]);
    } else {
        const int c    = (b - WBLKS) * 8 + (tid >> 5);
        const int lane = tid & 31;
        float4 v0 = make_float4(0.f, 0.f, 0.f, 0.f), v1 = v0;
        if (c < CNUM) {
            const float4* p4 = reinterpret_cast<const float4*>(P + (size_t)c * DDIM);
            v0 = p4[lane];
            v1 = p4[lane + 32];
        }
        __half2 h0[2] = { __floats2half2_rn(v0.x, v0.y), __floats2half2_rn(v0.z, v0.w) };
        __half2 h1[2] = { __floats2half2_rn(v1.x, v1.y), __floats2half2_rn(v1.z, v1.w) };
        if (c < CPAD) {
            *reinterpret_cast<uint2*>(&g_ph[c * DDIM + lane * 4])       = *reinterpret_cast<uint2*>(h0);
            *reinterpret_cast<uint2*>(&g_ph[c * DDIM + 128 + lane * 4]) = *reinterpret_cast<uint2*>(h1);
        }
        float s = v0.x * v0.x + v0.y * v0.y + v0.z * v0.z + v0.w * v0.w
                + v1.x * v1.x + v1.y * v1.y + v1.z * v1.z + v1.w * v1.w;
#pragma unroll
        for (int o = 16; o > 0; o >>= 1) s += __shfl_xor_sync(0xffffffffu, s, o);
        if (lane == 0 && c < CPAD) g_pn[c] = s;
    }
}

// ---------------------------------------------------------------------------
// Fused kernel: 256 thr / 8 warps, grid 128 (one wave, 1 CTA/SM).
// GEMM1 warp tile 64m x 64n (warp_m = wid&1, warp_n = wid>>1).
// A path: LDG x fp32 (2 iters ahead) -> cvt -> STS.128 fp16 (conflict-free).
// B path: cp.async from g_wt fp16, 3 stages.
// ---------------------------------------------------------------------------
__global__ void __launch_bounds__(NT, 1)
fused_kernel(const float* __restrict__ x,
             const float* __restrict__ bias,
             float* __restrict__ out)
{
    extern __shared__ __align__(16) unsigned char dyn[];
    __shared__ float s_bias[DDIM];
    __shared__ float srow[BM];
    __shared__ float s_pn[CPAD];

    const int tid  = threadIdx.x;
    const int wid  = tid >> 5;
    const int lane = tid & 31;
    const int lq = lane >> 2;
    const int lr = lane & 3;
    const int mBase = blockIdx.x * BM;

    const int warp_m = wid & 1;    // 0..1 : 64 rows
    const int warp_n = wid >> 1;   // 0..3 : 64 cols

    s_bias[tid] = bias[tid];       // NT == DDIM
    if (tid < BM)   srow[tid] = 0.0f;
    if (tid < CPAD) s_pn[tid] = g_pn[tid];

    const uint32_t dynb = smem_u32(dyn);

    // ---- A path: row = tid>>1 (0..127), half = tid&1 (32 floats each) ----
    const int arow = tid >> 1;
    const int aq   = tid & 1;
    const float4* xsrc = reinterpret_cast<const float4*>(
        x + (size_t)(mBase + arow) * KDIM + aq * 32);

    uint32_t hbuf[16];
    auto ldgA = [&](int kIter) {
        const float4* s = xsrc + kIter * (BK / 4);
#pragma unroll
        for (int j = 0; j < 8; j++) {
            float4 v = s[j];
            __half2 h0 = __floats2half2_rn(v.x, v.y);
            __half2 h1 = __floats2half2_rn(v.z, v.w);
            hbuf[2 * j]     = *reinterpret_cast<uint32_t*>(&h0);
            hbuf[2 * j + 1] = *reinterpret_cast<uint32_t*>(&h1);
        }
    };
    auto stsA = [&](int slot) {
        // word offset arow*36 + aq*16; STS.128 x4 -> conflict-free per phase
        uint4* d = reinterpret_cast<uint4*>(
            reinterpret_cast<uint32_t*>(dyn + slot * A_SLOT_BYTES)
            + arow * (AST / 2) + aq * 16);
#pragma unroll
        for (int j = 0; j < 4; j++)
            d[j] = make_uint4(hbuf[4 * j], hbuf[4 * j + 1],
                              hbuf[4 * j + 2], hbuf[4 * j + 3]);
    };

    // ---- B stage loader: 2048 chunks of 16B, 8/thread ----
    auto loadB = [&](int kIter, int slot) {
        const int k0 = kIter * BK;
        const uint32_t bB = dynb + B_OFF + slot * B_SLOT_BYTES;
#pragma unroll
        for (int i = 0; i < 8; i++) {
            const int c = tid + (i << 8);
            const int row = c >> 3, seg = c & 7;
            CP_ASYNC16(bB + row * (BST * 2) + seg * 16,
                       g_wt + (size_t)row * KDIM + k0 + seg * 8);
        }
    };

    // prologue
    ldgA(0); stsA(0); ldgA(1);
    loadB(0, 0); CP_COMMIT();
    loadB(1, 1); CP_COMMIT();

    float acc[4][8][4];
#pragma unroll
    for (int i = 0; i < 4; i++)
#pragma unroll
        for (int j = 0; j < 8; j++)
#pragma unroll
            for (int r = 0; r < 4; r++) acc[i][j][r] = 0.0f;

    for (int it = 0; it < NITER; ++it) {
        if (it == NITER - 1) { CP_WAIT0(); } else { CP_WAIT1(); }
        __syncthreads();

        if (it + 2 < NITER) { loadB(it + 2, (it + 2) % 3); CP_COMMIT(); }
        if (it + 1 < NITER) stsA((it + 1) & 1);
        if (it + 2 < NITER) ldgA(it + 2);

        const uint32_t* As = reinterpret_cast<const uint32_t*>(
            dyn + (it & 1) * A_SLOT_BYTES);
        const uint32_t* Bs = reinterpret_cast<const uint32_t*>(
            dyn + B_OFF + (it % 3) * B_SLOT_BYTES);
        const uint32_t* aP = As + (warp_m * 64 + lq) * (AST / 2) + lr;
        const uint32_t* bP = Bs + (warp_n * 64 + lq) * (BST / 2) + lr;

#pragma unroll
        for (int kk = 0; kk < 4; kk++) {
            uint32_t au[4][4], bu[8][2];
#pragma unroll
            for (int mi = 0; mi < 4; mi++) {
                const uint32_t* p = aP + mi * 16 * (AST / 2) + kk * 8;
                au[mi][0] = p[0];
                au[mi][1] = p[8 * (AST / 2)];
                au[mi][2] = p[4];
                au[mi][3] = p[8 * (AST / 2) + 4];
            }
#pragma unroll
            for (int nj = 0; nj < 8; nj++) {
                const uint32_t* p = bP + nj * 8 * (BST / 2) + kk * 8;
                bu[nj][0] = p[0];
                bu[nj][1] = p[4];
            }
#pragma unroll
            for (int mi = 0; mi < 4; mi++)
#pragma unroll
                for (int nj = 0; nj < 8; nj++)
                    MMA_F16(acc[mi][nj], au[mi], bu[nj]);
        }
    }
    __syncthreads();

    // ======================= epilogue A ====================================
    __half2* Zs2 = reinterpret_cast<__half2*>(dyn);
    const uint32_t pbu = dynb + ZS_BYTES;

    auto load_pchunk = [&](int kc, int buf) {
        const uint32_t base = pbu + buf * PCH_BYTES;
#pragma unroll
        for (int i = 0; i < 4; i++) {
            const int c = tid + (i << 8);
            if (c < CPAD * 8) {
                const int row = c >> 3, seg = c & 7;
                CP_ASYNC16(base + row * (PST * 2) + seg * 16,
                           g_ph + row * DDIM + kc * 64 + seg * 8);
            }
        }
    };
    load_pchunk(0, 0); CP_COMMIT();

    {
        float rsum[4][2];
#pragma unroll
        for (int mi = 0; mi < 4; mi++) { rsum[mi][0] = 0.f; rsum[mi][1] = 0.f; }

#pragma unroll
        for (int mi = 0; mi < 4; mi++) {
            const int rowA = warp_m * 64 + mi * 16 + lq;
#pragma unroll
            for (int nj = 0; nj < 8; nj++) {
                const int n0 = warp_n * 64 + nj * 8 + 2 * lr;
                float v0 = acc[mi][nj][0] + s_bias[n0];
                float v1 = acc[mi][nj][1] + s_bias[n0 + 1];
                float v2 = acc[mi][nj][2] + s_bias[n0];
                float v3 = acc[mi][nj][3] + s_bias[n0 + 1];
                rsum[mi][0] += v0 * v0 + v1 * v1;
                rsum[mi][1] += v2 * v2 + v3 * v3;
                Zs2[rowA * (ZST / 2) + (n0 >> 1)] = __floats2half2_rn(v0, v1);
                Zs2[(rowA + 8) * (ZST / 2) + (n0 >> 1)] = __floats2half2_rn(v2, v3);
            }
        }
#pragma unroll
        for (int mi = 0; mi < 4; mi++) {
#pragma unroll
            for (int h = 0; h < 2; h++) {
                float s = rsum[mi][h];
                s += __shfl_xor_sync(0xffffffffu, s, 1);
                s += __shfl_xor_sync(0xffffffffu, s, 2);
                if (lr == 0)
                    atomicAdd(&srow[warp_m * 64 + mi * 16 + lq + 8 * h], s);
            }
        }
    }

    // ======================= phase 2: MMA2 =================================
    const int warp_m2 = wid >> 1;   // 0..3 : 32 rows
    const int warp_n2 = wid & 1;    // 0..1 : 56 cols

    float acc2[2][7][4];
#pragma unroll
    for (int i = 0; i < 2; i++)
#pragma unroll
        for (int j = 0; j < 7; j++)
#pragma unroll
            for (int r = 0; r < 4; r++) acc2[i][j][r] = 0.0f;

    const uint32_t* Zs32 = reinterpret_cast<const uint32_t*>(dyn);

    for (int kc = 0; kc < 4; kc++) {
        if (kc + 1 < 4) { load_pchunk(kc + 1, (kc + 1) & 1); CP_COMMIT(); }
        if (kc + 1 < 4) { CP_WAIT1(); } else { CP_WAIT0(); }
        __syncthreads();

        const uint32_t* Ps = reinterpret_cast<const uint32_t*>(
            dyn + ZS_BYTES + (kc & 1) * PCH_BYTES);
        const uint32_t* pP = Ps + (warp_n2 * 56 + lq) * (PST / 2) + lr;

#pragma unroll
        for (int kk = 0; kk < 4; kk++) {
            uint32_t au[2][4], bu[7][2];
#pragma unroll
            for (int mi = 0; mi < 2; mi++) {
                const uint32_t* zp = Zs32
                    + (warp_m2 * 32 + mi * 16 + lq) * (ZST / 2)
                    + kc * 32 + kk * 8 + lr;
                au[mi][0] = zp[0];
                au[mi][1] = zp[8 * (ZST / 2)];
                au[mi][2] = zp[4];
                au[mi][3] = zp[8 * (ZST / 2) + 4];
            }
#pragma unroll
            for (int nj = 0; nj < 7; nj++) {
                const uint32_t* p = pP + nj * 8 * (PST / 2) + kk * 8;
                bu[nj][0] = p[0];
                bu[nj][1] = p[4];
            }
#pragma unroll
            for (int mi = 0; mi < 2; mi++)
#pragma unroll
                for (int nj = 0; nj < 7; nj++)
                    MMA_F16(acc2[mi][nj], au[mi], bu[nj]);
        }
        __syncthreads();
    }

    // ======================= epilogue B ====================================
    const float inv = 1.0f / (float)DDIM;
#pragma unroll
    for (int mi = 0; mi < 2; mi++) {
        const int rowA = warp_m2 * 32 + mi * 16 + lq;
        const int rowB = rowA + 8;
        const float rsA = srow[rowA];
        const float rsB = srow[rowB];
#pragma unroll
        for (int nj = 0; nj < 7; nj++) {
            const int c0 = warp_n2 * 56 + nj * 8 + 2 * lr;
            const float pn0 = s_pn[c0];
            const float pn1 = s_pn[c0 + 1];
            if (c0 < CNUM)
                out[(size_t)(mBase + rowA) * CNUM + c0] =
                    (2.0f * acc2[mi][nj][0] - rsA - pn0) * inv;
            if (c0 + 1 < CNUM)
                out[(size_t)(mBase + rowA) * CNUM + c0 + 1] =
                    (2.0f * acc2[mi][nj][1] - rsA - pn1) * inv;
            if (c0 < CNUM)
                out[(size_t)(mBase + rowB) * CNUM + c0] =
                    (2.0f * acc2[mi][nj][2] - rsB - pn0) * inv;
            if (c0 + 1 < CNUM)
                out[(size_t)(mBase + rowB) * CNUM + c0 + 1] =
                    (2.0f * acc2[mi][nj][3] - rsB - pn1) * inv;
        }
    }
}

// ---------------------------------------------------------------------------
extern "C" void kernel_launch(void* const* d_in, const int* in_sizes, int n_in,
                              void* d_out, int out_size)
{
    const float* x  = (const float*)d_in[0];
    const float* W  = (const float*)d_in[1];
    const float* b  = (const float*)d_in[2];
    const float* P  = (const float*)d_in[3];
    float* out = (float*)d_out;

    cudaFuncSetAttribute(fused_kernel,
                         cudaFuncAttributeMaxDynamicSharedMemorySize, DYN_BYTES);

    prep_kernel<<<PREP_GRID, 256>>>(W, P);
    fused_kernel<<<Bsz / BM, NT, DYN_BYTES>>>(x, b, out);
}